// round 3
// baseline (speedup 1.0000x reference)
#include <cuda_runtime.h>

#define N_NODES 100000
#define N_EDGES 800000

// ---------------- scratch (static __device__, no allocation) ----------------
__device__ __align__(16) float g_deg[N_NODES];
__device__ __align__(16) float g_dinv[N_NODES];
__device__ __align__(16) float g_norm[N_EDGES];
__device__ __align__(16) float g_T[(size_t)N_NODES * 128];
__device__ __align__(16) float g_A[(size_t)N_NODES * 128];
__device__ __align__(16) int   g_src[N_EDGES];
__device__ __align__(16) int   g_dst[N_EDGES];
__device__ int g_is64;

// ---------------- f32x2 packed-FMA helpers (sm_103a) ----------------
__device__ __forceinline__ unsigned long long dup_f32x2(float v) {
    unsigned long long r;
    unsigned int u = __float_as_uint(v);
    asm("mov.b64 %0, {%1, %1};" : "=l"(r) : "r"(u));
    return r;
}
__device__ __forceinline__ void fma_f32x2(unsigned long long& acc,
                                          unsigned long long a,
                                          unsigned long long b) {
    asm("fma.rn.f32x2 %0, %1, %2, %0;" : "+l"(acc) : "l"(a), "l"(b));
}
__device__ __forceinline__ float2 unpack_f32x2(unsigned long long v) {
    unsigned int lo, hi;
    asm("mov.b64 {%0, %1}, %2;" : "=r"(lo), "=r"(hi) : "l"(v));
    return make_float2(__uint_as_float(lo), __uint_as_float(hi));
}
__device__ __forceinline__ void red_add_v4(float* addr, float4 v) {
    asm volatile("red.relaxed.gpu.global.add.v4.f32 [%0], {%1, %2, %3, %4};"
                 :: "l"(addr), "f"(v.x), "f"(v.y), "f"(v.z), "f"(v.w)
                 : "memory");
}

// ---------------- edge-index dtype detection + conversion ----------------
__global__ void detect_kernel(const int* ei32) {
    if (threadIdx.x == 0 && blockIdx.x == 0) {
        int zeros = 0;
        for (int i = 0; i < 64; i++)
            if (ei32[2 * i + 1] == 0) zeros++;
        g_is64 = (zeros >= 60) ? 1 : 0;   // int64: every high word is 0
    }
}

__global__ void convert_kernel(const void* __restrict__ ei,
                               int* __restrict__ src, int* __restrict__ dst, int E) {
    int e = blockIdx.x * blockDim.x + threadIdx.x;
    if (e >= E) return;
    if (g_is64) {
        const long long* p = (const long long*)ei;
        src[e] = (int)p[e];
        dst[e] = (int)p[E + e];
    } else {
        const int* p = (const int*)ei;
        src[e] = p[e];
        dst[e] = p[E + e];
    }
}

// ---------------- degree / norm precompute ----------------
__global__ void zero_kernel(float* __restrict__ p, int n) {
    int i = blockIdx.x * blockDim.x + threadIdx.x;
    if (i < n) p[i] = 0.f;
}
__global__ void deg_kernel(const int* __restrict__ dst, float* __restrict__ deg, int E) {
    int e = blockIdx.x * blockDim.x + threadIdx.x;
    if (e < E) atomicAdd(&deg[dst[e]], 1.0f);
}
__global__ void dinv_kernel(const float* __restrict__ deg, float* __restrict__ dinv, int n) {
    int i = blockIdx.x * blockDim.x + threadIdx.x;
    if (i < n) dinv[i] = rsqrtf(deg[i] + 1.0f);
}
__global__ void norm_kernel(const int* __restrict__ src, const int* __restrict__ dst,
                            const float* __restrict__ dinv, float* __restrict__ nrm, int E) {
    int e = blockIdx.x * blockDim.x + threadIdx.x;
    if (e < E) nrm[e] = dinv[src[e]] * dinv[dst[e]];
}

// ---------------- fused GEMM:  T = relu?(X) @ W ;  A = T * dinv^2 + b ----------------
// K = 128 fixed. Block: 64 rows, FOUT cols, 256 threads, f32x2 packed FMAs.
template <int FOUT, bool RELU_IN>
__global__ void __launch_bounds__(256)
gemm_kernel(const float* __restrict__ X, const float* __restrict__ W,
            const float* __restrict__ bias, const float* __restrict__ dinv,
            float* __restrict__ T, float* __restrict__ A, int n) {
    extern __shared__ float smem[];
    float* Ws = smem;               // [128][FOUT]
    float* Xs = smem + 128 * FOUT;  // [64][128]
    const int tid = threadIdx.x;

    // stage W
    {
        const float4* Wg = reinterpret_cast<const float4*>(W);
        float4* Wd = reinterpret_cast<float4*>(Ws);
        for (int i = tid; i < 128 * FOUT / 4; i += 256) Wd[i] = Wg[i];
    }
    // stage X tile (ReLU applied on load for layers 2/3)
    const int row0 = blockIdx.x * 64;
    {
        const float4* Xg = reinterpret_cast<const float4*>(X);
        float4* Xd = reinterpret_cast<float4*>(Xs);
        for (int i = tid; i < 64 * 32; i += 256) {
            int r = i >> 5;
            float4 v = make_float4(0.f, 0.f, 0.f, 0.f);
            if (row0 + r < n) v = Xg[(size_t)(row0 + r) * 32 + (i & 31)];
            if (RELU_IN) {
                v.x = fmaxf(v.x, 0.f); v.y = fmaxf(v.y, 0.f);
                v.z = fmaxf(v.z, 0.f); v.w = fmaxf(v.w, 0.f);
            }
            Xd[i] = v;
        }
    }
    __syncthreads();

    constexpr int CGRP = FOUT / 8;           // col groups of 8 cols (=4 f32x2 pairs)
    constexpr int RPT  = 64 * CGRP / 256;    // rows per thread: 4 (FOUT=128) / 2 (FOUT=64)
    const int cg = tid % CGRP;
    const int rg = tid / CGRP;
    const int c0 = cg * 8;
    const int r0 = rg * RPT;

    unsigned long long acc[RPT][4];
#pragma unroll
    for (int i = 0; i < RPT; i++)
#pragma unroll
        for (int j = 0; j < 4; j++) acc[i][j] = 0ULL;

#pragma unroll 8
    for (int k = 0; k < 128; k += 2) {
        unsigned long long w[2][4];
#pragma unroll
        for (int kk = 0; kk < 2; kk++) {
            const ulonglong2* p =
                reinterpret_cast<const ulonglong2*>(&Ws[(k + kk) * FOUT + c0]);
            ulonglong2 u0 = p[0];
            ulonglong2 u1 = p[1];
            w[kk][0] = u0.x; w[kk][1] = u0.y; w[kk][2] = u1.x; w[kk][3] = u1.y;
        }
#pragma unroll
        for (int i = 0; i < RPT; i++) {
            float2 xv = *reinterpret_cast<const float2*>(&Xs[(r0 + i) * 128 + k]);
            unsigned long long x0 = dup_f32x2(xv.x);
            unsigned long long x1 = dup_f32x2(xv.y);
#pragma unroll
            for (int j = 0; j < 4; j++) {
                fma_f32x2(acc[i][j], x0, w[0][j]);
                fma_f32x2(acc[i][j], x1, w[1][j]);
            }
        }
    }

    // epilogue: T = acc ; A = acc * dinv^2 + bias
    float4 b0 = *reinterpret_cast<const float4*>(&bias[c0]);
    float4 b1 = *reinterpret_cast<const float4*>(&bias[c0 + 4]);
#pragma unroll
    for (int i = 0; i < RPT; i++) {
        int r = row0 + r0 + i;
        if (r >= n) continue;
        float dv = dinv[r];
        float sn = dv * dv;
        float o[8];
#pragma unroll
        for (int j = 0; j < 4; j++) {
            float2 p = unpack_f32x2(acc[i][j]);
            o[2 * j] = p.x;
            o[2 * j + 1] = p.y;
        }
        float4* Tp = reinterpret_cast<float4*>(&T[(size_t)r * FOUT + c0]);
        Tp[0] = make_float4(o[0], o[1], o[2], o[3]);
        Tp[1] = make_float4(o[4], o[5], o[6], o[7]);
        float4* Ap = reinterpret_cast<float4*>(&A[(size_t)r * FOUT + c0]);
        Ap[0] = make_float4(fmaf(o[0], sn, b0.x), fmaf(o[1], sn, b0.y),
                            fmaf(o[2], sn, b0.z), fmaf(o[3], sn, b0.w));
        Ap[1] = make_float4(fmaf(o[4], sn, b1.x), fmaf(o[5], sn, b1.y),
                            fmaf(o[6], sn, b1.z), fmaf(o[7], sn, b1.w));
    }
}

// ---------------- edge scatter:  A[dst] += T[src] * norm  (vector L2 reductions) ----------------
template <int F>
__global__ void __launch_bounds__(256)
scatter_kernel(const int* __restrict__ src, const int* __restrict__ dst,
               const float* __restrict__ nrm, const float* __restrict__ T,
               float* __restrict__ A, int E) {
    constexpr int LPE = F / 4;        // lanes per edge (float4 each)
    constexpr int SLOTS = 256 / LPE;  // concurrent edge slots per block
    __shared__ int s_src[256];
    __shared__ int s_dst[256];
    __shared__ float s_nm[256];
    const int tid = threadIdx.x;
    const int e0 = blockIdx.x * 256;
    int e = e0 + tid;
    if (e < E) {
        s_src[tid] = src[e];
        s_dst[tid] = dst[e];
        s_nm[tid] = nrm[e];
    }
    __syncthreads();
    const int lane = tid % LPE;
    const int imax = min(256, E - e0);
#pragma unroll 4
    for (int i = tid / LPE; i < imax; i += SLOTS) {
        int s = s_src[i];
        int d = s_dst[i];
        float nm = s_nm[i];
        float4 v = __ldg(&reinterpret_cast<const float4*>(T)[(size_t)s * LPE + lane]);
        v.x *= nm; v.y *= nm; v.z *= nm; v.w *= nm;
        red_add_v4(&A[(size_t)d * F + lane * 4], v);
    }
}

// ---------------- launch ----------------
extern "C" void kernel_launch(void* const* d_in, const int* in_sizes, int n_in,
                              void* d_out, int out_size) {
    const float* x  = (const float*)d_in[0];
    const void*  ei = d_in[1];
    const float* W1 = (const float*)d_in[2];
    const float* b1 = (const float*)d_in[3];
    const float* W2 = (const float*)d_in[4];
    const float* b2 = (const float*)d_in[5];
    const float* W3 = (const float*)d_in[6];
    const float* b3 = (const float*)d_in[7];
    float* out = (float*)d_out;

    float *deg, *dinv, *nrm, *T, *A;
    int *src, *dst;
    cudaGetSymbolAddress((void**)&deg, g_deg);
    cudaGetSymbolAddress((void**)&dinv, g_dinv);
    cudaGetSymbolAddress((void**)&nrm, g_norm);
    cudaGetSymbolAddress((void**)&T, g_T);
    cudaGetSymbolAddress((void**)&A, g_A);
    cudaGetSymbolAddress((void**)&src, g_src);
    cudaGetSymbolAddress((void**)&dst, g_dst);

    const int SMEM128 = (128 * 128 + 64 * 128) * 4;  // 96 KB
    const int SMEM64  = (128 * 64 + 64 * 128) * 4;   // 64 KB
    cudaFuncSetAttribute(gemm_kernel<128, false>,
                         cudaFuncAttributeMaxDynamicSharedMemorySize, SMEM128);
    cudaFuncSetAttribute(gemm_kernel<128, true>,
                         cudaFuncAttributeMaxDynamicSharedMemorySize, SMEM128);
    cudaFuncSetAttribute(gemm_kernel<64, true>,
                         cudaFuncAttributeMaxDynamicSharedMemorySize, SMEM64);

    const int N = N_NODES;
    const int E = N_EDGES;
    const int eb = (E + 255) / 256;
    const int nb = (N + 255) / 256;
    const int gb = (N + 63) / 64;

    detect_kernel<<<1, 32>>>((const int*)ei);
    convert_kernel<<<eb, 256>>>(ei, src, dst, E);
    zero_kernel<<<nb, 256>>>(deg, N);
    deg_kernel<<<eb, 256>>>(dst, deg, E);
    dinv_kernel<<<nb, 256>>>(deg, dinv, N);
    norm_kernel<<<eb, 256>>>(src, dst, dinv, nrm, E);

    // layer 1
    gemm_kernel<128, false><<<gb, 256, SMEM128>>>(x, W1, b1, dinv, T, A, N);
    scatter_kernel<128><<<eb, 256>>>(src, dst, nrm, T, A, E);
    // layer 2 (ReLU of A applied on load; in-place A is safe: blocks own disjoint rows)
    gemm_kernel<128, true><<<gb, 256, SMEM128>>>(A, W2, b2, dinv, T, A, N);
    scatter_kernel<128><<<eb, 256>>>(src, dst, nrm, T, A, E);
    // layer 3 -> d_out (epilogue fully initializes d_out before atomics)
    gemm_kernel<64, true><<<gb, 256, SMEM64>>>(A, W3, b3, dinv, T, out, N);
    scatter_kernel<64><<<eb, 256>>>(src, dst, nrm, T, out, E);
}

// round 6
// speedup vs baseline: 1.0060x; 1.0060x over previous
#include <cuda_runtime.h>

#define N_NODES 100000
#define N_EDGES 800000

// ---------------- scratch (static __device__, no allocation) ----------------
__device__ __align__(16) float g_dinv[N_NODES];
__device__ __align__(16) int   g_cnt[N_NODES];
__device__ __align__(16) int   g_off[N_NODES];
__device__ __align__(16) int   g_cur[N_NODES];
__device__ __align__(16) int2  g_csr[N_EDGES];     // {src, norm-as-int}
__device__ __align__(16) float g_T[(size_t)N_NODES * 128];
__device__ __align__(16) float g_A[(size_t)N_NODES * 128];
__device__ __align__(16) int   g_src[N_EDGES];
__device__ __align__(16) int   g_dst[N_EDGES];
__device__ __align__(16) int   g_bsum[512];
__device__ int g_is64;

// ---------------- f32x2 packed-FMA helpers (sm_103a) ----------------
__device__ __forceinline__ unsigned long long dup_f32x2(float v) {
    unsigned long long r;
    unsigned int u = __float_as_uint(v);
    asm("mov.b64 %0, {%1, %1};" : "=l"(r) : "r"(u));
    return r;
}
__device__ __forceinline__ void fma_f32x2(unsigned long long& acc,
                                          unsigned long long a,
                                          unsigned long long b) {
    asm("fma.rn.f32x2 %0, %1, %2, %0;" : "+l"(acc) : "l"(a), "l"(b));
}
__device__ __forceinline__ float2 unpack_f32x2(unsigned long long v) {
    unsigned int lo, hi;
    asm("mov.b64 {%0, %1}, %2;" : "=r"(lo), "=r"(hi) : "l"(v));
    return make_float2(__uint_as_float(lo), __uint_as_float(hi));
}

// ---------------- edge-index dtype detection ----------------
__global__ void detect_kernel(const int* ei32) {
    if (threadIdx.x == 0 && blockIdx.x == 0) {
        int zeros = 0;
        for (int i = 0; i < 64; i++)
            if (ei32[2 * i + 1] == 0) zeros++;
        g_is64 = (zeros >= 60) ? 1 : 0;   // int64: every high word is 0
    }
}

__global__ void zero_cnt_kernel(int* __restrict__ cnt, int n) {
    int i = blockIdx.x * blockDim.x + threadIdx.x;
    if (i < n) cnt[i] = 0;
}

// convert edge index to int32 src/dst AND count in-degree per dst
__global__ void convert_count_kernel(const void* __restrict__ ei,
                                     int* __restrict__ src, int* __restrict__ dst,
                                     int* __restrict__ cnt, int E) {
    int e = blockIdx.x * blockDim.x + threadIdx.x;
    if (e >= E) return;
    int s, d;
    if (g_is64) {
        const long long* p = (const long long*)ei;
        s = (int)p[e];
        d = (int)p[E + e];
    } else {
        const int* p = (const int*)ei;
        s = p[e];
        d = p[E + e];
    }
    src[e] = s;
    dst[e] = d;
    atomicAdd(&cnt[d], 1);
}

__global__ void dinv_kernel(const int* __restrict__ cnt, float* __restrict__ dinv, int n) {
    int i = blockIdx.x * blockDim.x + threadIdx.x;
    if (i < n) dinv[i] = rsqrtf((float)cnt[i] + 1.0f);
}

// ---------------- exclusive scan of cnt -> off (3 stages) ----------------
__global__ void scan1_kernel(const int* __restrict__ cnt, int* __restrict__ partial,
                             int* __restrict__ bsum, int n) {
    __shared__ int sh[256];
    const int tid = threadIdx.x;
    const int i = blockIdx.x * 256 + tid;
    int v = (i < n) ? cnt[i] : 0;
    sh[tid] = v;
    __syncthreads();
    for (int d = 1; d < 256; d <<= 1) {
        int t = (tid >= d) ? sh[tid - d] : 0;
        __syncthreads();
        sh[tid] += t;
        __syncthreads();
    }
    if (i < n) partial[i] = sh[tid] - v;   // exclusive within block
    if (tid == 255) bsum[blockIdx.x] = sh[255];
}

__global__ void scan2_kernel(int* __restrict__ bsum, int nb) {
    __shared__ int sh[512];
    const int tid = threadIdx.x;
    int v = (tid < nb) ? bsum[tid] : 0;
    sh[tid] = v;
    __syncthreads();
    for (int d = 1; d < 512; d <<= 1) {
        int t = (tid >= d) ? sh[tid - d] : 0;
        __syncthreads();
        sh[tid] += t;
        __syncthreads();
    }
    if (tid < nb) bsum[tid] = sh[tid] - v;  // exclusive
}

__global__ void scan3_kernel(int* __restrict__ off, int* __restrict__ cur,
                             const int* __restrict__ bsum, int n) {
    int i = blockIdx.x * blockDim.x + threadIdx.x;
    if (i >= n) return;
    int o = off[i] + bsum[blockIdx.x];
    off[i] = o;
    cur[i] = o;
}

// ---------------- CSR bucket fill: csr[pos] = {src, norm} ----------------
__global__ void csr_build_kernel(const int* __restrict__ src, const int* __restrict__ dst,
                                 const float* __restrict__ dinv, int* __restrict__ cur,
                                 int2* __restrict__ csr, int E) {
    int e = blockIdx.x * blockDim.x + threadIdx.x;
    if (e >= E) return;
    int s = src[e];
    int d = dst[e];
    float nm = __ldg(&dinv[s]) * __ldg(&dinv[d]);
    int pos = atomicAdd(&cur[d], 1);
    csr[pos] = make_int2(s, __float_as_int(nm));
}

// ---------------- fused GEMM:  T = relu?(X) @ W ;  A = T * dinv^2 + b ----------------
// K = 128 fixed. Block: 64 rows, FOUT cols, 256 threads, f32x2 packed FMAs.
template <int FOUT, bool RELU_IN>
__global__ void __launch_bounds__(256)
gemm_kernel(const float* __restrict__ X, const float* __restrict__ W,
            const float* __restrict__ bias, const float* __restrict__ dinv,
            float* __restrict__ T, float* __restrict__ A, int n) {
    extern __shared__ float smem[];
    float* Ws = smem;               // [128][FOUT]
    float* Xs = smem + 128 * FOUT;  // [64][128]
    const int tid = threadIdx.x;

    // stage W
    {
        const float4* Wg = reinterpret_cast<const float4*>(W);
        float4* Wd = reinterpret_cast<float4*>(Ws);
        for (int i = tid; i < 128 * FOUT / 4; i += 256) Wd[i] = Wg[i];
    }
    // stage X tile (ReLU applied on load for layers 2/3)
    const int row0 = blockIdx.x * 64;
    {
        const float4* Xg = reinterpret_cast<const float4*>(X);
        float4* Xd = reinterpret_cast<float4*>(Xs);
        for (int i = tid; i < 64 * 32; i += 256) {
            int r = i >> 5;
            float4 v = make_float4(0.f, 0.f, 0.f, 0.f);
            if (row0 + r < n) v = Xg[(size_t)(row0 + r) * 32 + (i & 31)];
            if (RELU_IN) {
                v.x = fmaxf(v.x, 0.f); v.y = fmaxf(v.y, 0.f);
                v.z = fmaxf(v.z, 0.f); v.w = fmaxf(v.w, 0.f);
            }
            Xd[i] = v;
        }
    }
    __syncthreads();

    constexpr int CGRP = FOUT / 8;           // col groups of 8 cols (=4 f32x2 pairs)
    constexpr int RPT  = 64 * CGRP / 256;    // rows per thread: 4 (FOUT=128) / 2 (FOUT=64)
    const int cg = tid % CGRP;
    const int rg = tid / CGRP;
    const int c0 = cg * 8;
    const int r0 = rg * RPT;

    unsigned long long acc[RPT][4];
#pragma unroll
    for (int i = 0; i < RPT; i++)
#pragma unroll
        for (int j = 0; j < 4; j++) acc[i][j] = 0ULL;

#pragma unroll 8
    for (int k = 0; k < 128; k += 2) {
        unsigned long long w[2][4];
#pragma unroll
        for (int kk = 0; kk < 2; kk++) {
            const ulonglong2* p =
                reinterpret_cast<const ulonglong2*>(&Ws[(k + kk) * FOUT + c0]);
            ulonglong2 u0 = p[0];
            ulonglong2 u1 = p[1];
            w[kk][0] = u0.x; w[kk][1] = u0.y; w[kk][2] = u1.x; w[kk][3] = u1.y;
        }
#pragma unroll
        for (int i = 0; i < RPT; i++) {
            float2 xv = *reinterpret_cast<const float2*>(&Xs[(r0 + i) * 128 + k]);
            unsigned long long x0 = dup_f32x2(xv.x);
            unsigned long long x1 = dup_f32x2(xv.y);
#pragma unroll
            for (int j = 0; j < 4; j++) {
                fma_f32x2(acc[i][j], x0, w[0][j]);
                fma_f32x2(acc[i][j], x1, w[1][j]);
            }
        }
    }

    // epilogue: T = acc ; A = acc * dinv^2 + bias
    float4 b0 = *reinterpret_cast<const float4*>(&bias[c0]);
    float4 b1 = *reinterpret_cast<const float4*>(&bias[c0 + 4]);
#pragma unroll
    for (int i = 0; i < RPT; i++) {
        int r = row0 + r0 + i;
        if (r >= n) continue;
        float dv = dinv[r];
        float sn = dv * dv;
        float o[8];
#pragma unroll
        for (int j = 0; j < 4; j++) {
            float2 p = unpack_f32x2(acc[i][j]);
            o[2 * j] = p.x;
            o[2 * j + 1] = p.y;
        }
        float4* Tp = reinterpret_cast<float4*>(&T[(size_t)r * FOUT + c0]);
        Tp[0] = make_float4(o[0], o[1], o[2], o[3]);
        Tp[1] = make_float4(o[4], o[5], o[6], o[7]);
        float4* Ap = reinterpret_cast<float4*>(&A[(size_t)r * FOUT + c0]);
        Ap[0] = make_float4(fmaf(o[0], sn, b0.x), fmaf(o[1], sn, b0.y),
                            fmaf(o[2], sn, b0.z), fmaf(o[3], sn, b0.w));
        Ap[1] = make_float4(fmaf(o[4], sn, b1.x), fmaf(o[5], sn, b1.y),
                            fmaf(o[6], sn, b1.z), fmaf(o[7], sn, b1.w));
    }
}

// ---------------- pull aggregation: A[d] += sum_{e in CSR[d]} T[src_e] * nrm_e ----------------
// One F/4-lane group per node; register accumulation; single regular store. No atomics.
template <int F>
__global__ void __launch_bounds__(256)
agg_kernel(const int* __restrict__ off, const int* __restrict__ cnt,
           const int2* __restrict__ csr, const float* __restrict__ T,
           float* __restrict__ A, int n) {
    constexpr int GRP = F / 4;          // float4 lanes per node (32 or 16)
    constexpr int NPB = 256 / GRP;      // nodes per block (8 or 16)
    const int lane = threadIdx.x % GRP;
    const int node = blockIdx.x * NPB + threadIdx.x / GRP;
    if (node >= n) return;

    const int beg = off[node];
    const int m = cnt[node];
    const float4* __restrict__ Tv = reinterpret_cast<const float4*>(T);
    float4* __restrict__ Av = reinterpret_cast<float4*>(A);

    float4 acc = Av[(size_t)node * GRP + lane];   // self-loop + bias (from gemm epilogue)

    int e = 0;
    for (; e + 4 <= m; e += 4) {
        int2 p0 = __ldg(&csr[beg + e + 0]);
        int2 p1 = __ldg(&csr[beg + e + 1]);
        int2 p2 = __ldg(&csr[beg + e + 2]);
        int2 p3 = __ldg(&csr[beg + e + 3]);
        float4 v0 = __ldg(&Tv[(size_t)p0.x * GRP + lane]);
        float4 v1 = __ldg(&Tv[(size_t)p1.x * GRP + lane]);
        float4 v2 = __ldg(&Tv[(size_t)p2.x * GRP + lane]);
        float4 v3 = __ldg(&Tv[(size_t)p3.x * GRP + lane]);
        float n0 = __int_as_float(p0.y), n1 = __int_as_float(p1.y);
        float n2 = __int_as_float(p2.y), n3 = __int_as_float(p3.y);
        acc.x = fmaf(v0.x, n0, acc.x); acc.y = fmaf(v0.y, n0, acc.y);
        acc.z = fmaf(v0.z, n0, acc.z); acc.w = fmaf(v0.w, n0, acc.w);
        acc.x = fmaf(v1.x, n1, acc.x); acc.y = fmaf(v1.y, n1, acc.y);
        acc.z = fmaf(v1.z, n1, acc.z); acc.w = fmaf(v1.w, n1, acc.w);
        acc.x = fmaf(v2.x, n2, acc.x); acc.y = fmaf(v2.y, n2, acc.y);
        acc.z = fmaf(v2.z, n2, acc.z); acc.w = fmaf(v2.w, n2, acc.w);
        acc.x = fmaf(v3.x, n3, acc.x); acc.y = fmaf(v3.y, n3, acc.y);
        acc.z = fmaf(v3.z, n3, acc.z); acc.w = fmaf(v3.w, n3, acc.w);
    }
    for (; e < m; e++) {
        int2 p = __ldg(&csr[beg + e]);
        float4 v = __ldg(&Tv[(size_t)p.x * GRP + lane]);
        float nm = __int_as_float(p.y);
        acc.x = fmaf(v.x, nm, acc.x); acc.y = fmaf(v.y, nm, acc.y);
        acc.z = fmaf(v.z, nm, acc.z); acc.w = fmaf(v.w, nm, acc.w);
    }
    Av[(size_t)node * GRP + lane] = acc;
}

// ---------------- launch ----------------
extern "C" void kernel_launch(void* const* d_in, const int* in_sizes, int n_in,
                              void* d_out, int out_size) {
    const float* x  = (const float*)d_in[0];
    const void*  ei = d_in[1];
    const float* W1 = (const float*)d_in[2];
    const float* b1 = (const float*)d_in[3];
    const float* W2 = (const float*)d_in[4];
    const float* b2 = (const float*)d_in[5];
    const float* W3 = (const float*)d_in[6];
    const float* b3 = (const float*)d_in[7];
    float* out = (float*)d_out;

    float *dinv, *T, *A;
    int *cnt, *off, *cur, *src, *dst, *bsum;
    int2* csr;
    cudaGetSymbolAddress((void**)&dinv, g_dinv);
    cudaGetSymbolAddress((void**)&cnt, g_cnt);
    cudaGetSymbolAddress((void**)&off, g_off);
    cudaGetSymbolAddress((void**)&cur, g_cur);
    cudaGetSymbolAddress((void**)&csr, g_csr);
    cudaGetSymbolAddress((void**)&T, g_T);
    cudaGetSymbolAddress((void**)&A, g_A);
    cudaGetSymbolAddress((void**)&src, g_src);
    cudaGetSymbolAddress((void**)&dst, g_dst);
    cudaGetSymbolAddress((void**)&bsum, g_bsum);

    const int SMEM128 = (128 * 128 + 64 * 128) * 4;  // 96 KB
    const int SMEM64  = (128 * 64 + 64 * 128) * 4;   // 64 KB
    cudaFuncSetAttribute(gemm_kernel<128, false>,
                         cudaFuncAttributeMaxDynamicSharedMemorySize, SMEM128);
    cudaFuncSetAttribute(gemm_kernel<128, true>,
                         cudaFuncAttributeMaxDynamicSharedMemorySize, SMEM128);
    cudaFuncSetAttribute(gemm_kernel<64, true>,
                         cudaFuncAttributeMaxDynamicSharedMemorySize, SMEM64);

    const int N = N_NODES;
    const int E = N_EDGES;
    const int eb = (E + 255) / 256;
    const int nb = (N + 255) / 256;   // 391 blocks <= 512 (scan2 capacity)
    const int gb = (N + 63) / 64;

    // graph preprocessing -> CSR by dst
    detect_kernel<<<1, 32>>>((const int*)ei);
    zero_cnt_kernel<<<nb, 256>>>(cnt, N);
    convert_count_kernel<<<eb, 256>>>(ei, src, dst, cnt, E);
    dinv_kernel<<<nb, 256>>>(cnt, dinv, N);
    scan1_kernel<<<nb, 256>>>(cnt, off, bsum, N);
    scan2_kernel<<<1, 512>>>(bsum, nb);
    scan3_kernel<<<nb, 256>>>(off, cur, bsum, N);
    csr_build_kernel<<<eb, 256>>>(src, dst, dinv, cur, csr, E);

    // layer 1
    gemm_kernel<128, false><<<gb, 256, SMEM128>>>(x, W1, b1, dinv, T, A, N);
    agg_kernel<128><<<(N + 7) / 8, 256>>>(off, cnt, csr, T, A, N);
    // layer 2 (ReLU of A applied on load in gemm)
    gemm_kernel<128, true><<<gb, 256, SMEM128>>>(A, W2, b2, dinv, T, A, N);
    agg_kernel<128><<<(N + 7) / 8, 256>>>(off, cnt, csr, T, A, N);
    // layer 3 -> d_out (gemm epilogue fully initializes out; agg updates in place)
    gemm_kernel<64, true><<<gb, 256, SMEM64>>>(A, W3, b3, dinv, T, out, N);
    agg_kernel<64><<<(N + 15) / 16, 256>>>(off, cnt, csr, T, out, N);
}

// round 11
// speedup vs baseline: 1.1253x; 1.1185x over previous
#include <cuda_runtime.h>

#define N_NODES 100000
#define N_EDGES 800000

// ---------------- scratch (static __device__, no allocation) ----------------
__device__ __align__(16) float g_dinv[N_NODES];
__device__ __align__(16) int   g_cnt[N_NODES];
__device__ __align__(16) int   g_off[N_NODES];
__device__ __align__(16) int   g_cur[N_NODES];
__device__ __align__(16) int2  g_csr[N_EDGES];     // {src, norm-as-int}
__device__ __align__(16) float g_T[(size_t)N_NODES * 128];
__device__ __align__(16) float g_A[(size_t)N_NODES * 128];
__device__ __align__(16) int   g_src[N_EDGES];
__device__ __align__(16) int   g_dst[N_EDGES];
__device__ __align__(16) int   g_bsum[512];

// ---------------- f32x2 packed-FMA helpers (sm_103a) ----------------
__device__ __forceinline__ unsigned long long dup_f32x2(float v) {
    unsigned long long r;
    unsigned int u = __float_as_uint(v);
    asm("mov.b64 %0, {%1, %1};" : "=l"(r) : "r"(u));
    return r;
}
__device__ __forceinline__ void fma_f32x2(unsigned long long& acc,
                                          unsigned long long a,
                                          unsigned long long b) {
    asm("fma.rn.f32x2 %0, %1, %2, %0;" : "+l"(acc) : "l"(a), "l"(b));
}
__device__ __forceinline__ float2 unpack_f32x2(unsigned long long v) {
    unsigned int lo, hi;
    asm("mov.b64 {%0, %1}, %2;" : "=r"(lo), "=r"(hi) : "l"(v));
    return make_float2(__uint_as_float(lo), __uint_as_float(hi));
}

// ---------------- launch 1: zero cnt ----------------
__global__ void zero_cnt_kernel(int* __restrict__ cnt, int n) {
    int i = blockIdx.x * blockDim.x + threadIdx.x;
    if (i < n) cnt[i] = 0;
}

// ---------------- launch 2: convert + count (dtype detect inlined per block) ----------------
__global__ void convert_count_kernel(const void* __restrict__ ei,
                                     int* __restrict__ src, int* __restrict__ dst,
                                     int* __restrict__ cnt, int E) {
    __shared__ int s_is64;
    if (threadIdx.x < 32) {
        // int64 edge index read as int pairs: every high word is 0 (ids < 2^31)
        int v = ((const int*)ei)[2 * threadIdx.x + 1];
        unsigned b = __ballot_sync(0xffffffffu, v == 0);
        if (threadIdx.x == 0) s_is64 = (__popc(b) >= 30) ? 1 : 0;
    }
    __syncthreads();
    int e = blockIdx.x * blockDim.x + threadIdx.x;
    if (e >= E) return;
    int s, d;
    if (s_is64) {
        const long long* p = (const long long*)ei;
        s = (int)p[e];
        d = (int)p[E + e];
    } else {
        const int* p = (const int*)ei;
        s = p[e];
        d = p[E + e];
    }
    src[e] = s;
    dst[e] = d;
    atomicAdd(&cnt[d], 1);
}

// ---------------- launch 3: per-block scan of cnt + dinv (fused) ----------------
__global__ void scan1_dinv_kernel(const int* __restrict__ cnt, int* __restrict__ partial,
                                  int* __restrict__ bsum, float* __restrict__ dinv, int n) {
    __shared__ int sh[256];
    const int tid = threadIdx.x;
    const int i = blockIdx.x * 256 + tid;
    int v = (i < n) ? cnt[i] : 0;
    if (i < n) dinv[i] = rsqrtf((float)v + 1.0f);
    sh[tid] = v;
    __syncthreads();
    for (int d = 1; d < 256; d <<= 1) {
        int t = (tid >= d) ? sh[tid - d] : 0;
        __syncthreads();
        sh[tid] += t;
        __syncthreads();
    }
    if (i < n) partial[i] = sh[tid] - v;   // exclusive within block
    if (tid == 255) bsum[blockIdx.x] = sh[255];
}

// ---------------- launch 5: scan of block sums ----------------
__global__ void scan2_kernel(int* __restrict__ bsum, int nb) {
    __shared__ int sh[512];
    const int tid = threadIdx.x;
    int v = (tid < nb) ? bsum[tid] : 0;
    sh[tid] = v;
    __syncthreads();
    for (int d = 1; d < 512; d <<= 1) {
        int t = (tid >= d) ? sh[tid - d] : 0;
        __syncthreads();
        sh[tid] += t;
        __syncthreads();
    }
    if (tid < nb) bsum[tid] = sh[tid] - v;  // exclusive
}

// ---------------- launch 6: add block base; init bucket cursors ----------------
__global__ void scan3_kernel(int* __restrict__ off, int* __restrict__ cur,
                             const int* __restrict__ bsum, int n) {
    int i = blockIdx.x * blockDim.x + threadIdx.x;
    if (i >= n) return;
    int o = off[i] + bsum[blockIdx.x];
    off[i] = o;
    cur[i] = o;
}

// ---------------- launch 7: CSR bucket fill: csr[pos] = {src, norm} ----------------
__global__ void csr_build_kernel(const int* __restrict__ src, const int* __restrict__ dst,
                                 const float* __restrict__ dinv, int* __restrict__ cur,
                                 int2* __restrict__ csr, int E) {
    int e = blockIdx.x * blockDim.x + threadIdx.x;
    if (e >= E) return;
    int s = src[e];
    int d = dst[e];
    float nm = __ldg(&dinv[s]) * __ldg(&dinv[d]);
    int pos = atomicAdd(&cur[d], 1);
    csr[pos] = make_int2(s, __float_as_int(nm));
}

// ---------------- GEMM:  T = relu?(X) @ W  (no epilogue beyond the store) ----------------
// K = 128 fixed. Block: 64 rows, FOUT cols, 256 threads, f32x2 packed FMAs.
template <int FOUT, bool RELU_IN>
__global__ void __launch_bounds__(256)
gemm_kernel(const float* __restrict__ X, const float* __restrict__ W,
            float* __restrict__ T, int n) {
    extern __shared__ float smem[];
    float* Ws = smem;               // [128][FOUT]
    float* Xs = smem + 128 * FOUT;  // [64][128]
    const int tid = threadIdx.x;

    // stage W
    {
        const float4* Wg = reinterpret_cast<const float4*>(W);
        float4* Wd = reinterpret_cast<float4*>(Ws);
        for (int i = tid; i < 128 * FOUT / 4; i += 256) Wd[i] = Wg[i];
    }
    // stage X tile (ReLU applied on load for layers 2/3)
    const int row0 = blockIdx.x * 64;
    {
        const float4* Xg = reinterpret_cast<const float4*>(X);
        float4* Xd = reinterpret_cast<float4*>(Xs);
        for (int i = tid; i < 64 * 32; i += 256) {
            int r = i >> 5;
            float4 v = make_float4(0.f, 0.f, 0.f, 0.f);
            if (row0 + r < n) v = Xg[(size_t)(row0 + r) * 32 + (i & 31)];
            if (RELU_IN) {
                v.x = fmaxf(v.x, 0.f); v.y = fmaxf(v.y, 0.f);
                v.z = fmaxf(v.z, 0.f); v.w = fmaxf(v.w, 0.f);
            }
            Xd[i] = v;
        }
    }
    __syncthreads();

    constexpr int CGRP = FOUT / 8;           // col groups of 8 cols (=4 f32x2 pairs)
    constexpr int RPT  = 64 * CGRP / 256;    // rows per thread: 4 (FOUT=128) / 2 (FOUT=64)
    const int cg = tid % CGRP;
    const int rg = tid / CGRP;
    const int c0 = cg * 8;
    const int r0 = rg * RPT;

    unsigned long long acc[RPT][4];
#pragma unroll
    for (int i = 0; i < RPT; i++)
#pragma unroll
        for (int j = 0; j < 4; j++) acc[i][j] = 0ULL;

#pragma unroll 8
    for (int k = 0; k < 128; k += 2) {
        unsigned long long w[2][4];
#pragma unroll
        for (int kk = 0; kk < 2; kk++) {
            const ulonglong2* p =
                reinterpret_cast<const ulonglong2*>(&Ws[(k + kk) * FOUT + c0]);
            ulonglong2 u0 = p[0];
            ulonglong2 u1 = p[1];
            w[kk][0] = u0.x; w[kk][1] = u0.y; w[kk][2] = u1.x; w[kk][3] = u1.y;
        }
#pragma unroll
        for (int i = 0; i < RPT; i++) {
            float2 xv = *reinterpret_cast<const float2*>(&Xs[(r0 + i) * 128 + k]);
            unsigned long long x0 = dup_f32x2(xv.x);
            unsigned long long x1 = dup_f32x2(xv.y);
#pragma unroll
            for (int j = 0; j < 4; j++) {
                fma_f32x2(acc[i][j], x0, w[0][j]);
                fma_f32x2(acc[i][j], x1, w[1][j]);
            }
        }
    }

    // epilogue: store T only
#pragma unroll
    for (int i = 0; i < RPT; i++) {
        int r = row0 + r0 + i;
        if (r >= n) continue;
        float o[8];
#pragma unroll
        for (int j = 0; j < 4; j++) {
            float2 p = unpack_f32x2(acc[i][j]);
            o[2 * j] = p.x;
            o[2 * j + 1] = p.y;
        }
        float4* Tp = reinterpret_cast<float4*>(&T[(size_t)r * FOUT + c0]);
        Tp[0] = make_float4(o[0], o[1], o[2], o[3]);
        Tp[1] = make_float4(o[4], o[5], o[6], o[7]);
    }
}

// ---------------- pull aggregation (full GCN combine):
//   A[d] = bias + T[d]*dinv[d]^2 + sum_{e in CSR[d]} T[src_e]*nrm_e
// One F/4-lane group per node; register accumulation; single store; no atomics.
template <int F>
__global__ void __launch_bounds__(256)
agg_kernel(const int* __restrict__ off, const int* __restrict__ cnt,
           const int2* __restrict__ csr, const float* __restrict__ T,
           const float* __restrict__ bias, const float* __restrict__ dinv,
           float* __restrict__ A, int n) {
    constexpr int GRP = F / 4;          // float4 lanes per node (32 or 16)
    constexpr int NPB = 256 / GRP;      // nodes per block (8 or 16)
    const int lane = threadIdx.x % GRP;
    const int node = blockIdx.x * NPB + threadIdx.x / GRP;
    if (node >= n) return;

    const int beg = off[node];
    const int m = cnt[node];
    const float4* __restrict__ Tv = reinterpret_cast<const float4*>(T);

    // self-loop + bias
    float dv = __ldg(&dinv[node]);
    float sn = dv * dv;
    float4 b = __ldg(&reinterpret_cast<const float4*>(bias)[lane]);
    float4 tn = __ldg(&Tv[(size_t)node * GRP + lane]);
    float4 acc = make_float4(fmaf(tn.x, sn, b.x), fmaf(tn.y, sn, b.y),
                             fmaf(tn.z, sn, b.z), fmaf(tn.w, sn, b.w));

    int e = 0;
    for (; e + 4 <= m; e += 4) {
        int2 p0 = __ldg(&csr[beg + e + 0]);
        int2 p1 = __ldg(&csr[beg + e + 1]);
        int2 p2 = __ldg(&csr[beg + e + 2]);
        int2 p3 = __ldg(&csr[beg + e + 3]);
        float4 v0 = __ldg(&Tv[(size_t)p0.x * GRP + lane]);
        float4 v1 = __ldg(&Tv[(size_t)p1.x * GRP + lane]);
        float4 v2 = __ldg(&Tv[(size_t)p2.x * GRP + lane]);
        float4 v3 = __ldg(&Tv[(size_t)p3.x * GRP + lane]);
        float n0 = __int_as_float(p0.y), n1 = __int_as_float(p1.y);
        float n2 = __int_as_float(p2.y), n3 = __int_as_float(p3.y);
        acc.x = fmaf(v0.x, n0, acc.x); acc.y = fmaf(v0.y, n0, acc.y);
        acc.z = fmaf(v0.z, n0, acc.z); acc.w = fmaf(v0.w, n0, acc.w);
        acc.x = fmaf(v1.x, n1, acc.x); acc.y = fmaf(v1.y, n1, acc.y);
        acc.z = fmaf(v1.z, n1, acc.z); acc.w = fmaf(v1.w, n1, acc.w);
        acc.x = fmaf(v2.x, n2, acc.x); acc.y = fmaf(v2.y, n2, acc.y);
        acc.z = fmaf(v2.z, n2, acc.z); acc.w = fmaf(v2.w, n2, acc.w);
        acc.x = fmaf(v3.x, n3, acc.x); acc.y = fmaf(v3.y, n3, acc.y);
        acc.z = fmaf(v3.z, n3, acc.z); acc.w = fmaf(v3.w, n3, acc.w);
    }
    for (; e < m; e++) {
        int2 p = __ldg(&csr[beg + e]);
        float4 v = __ldg(&Tv[(size_t)p.x * GRP + lane]);
        float nm = __int_as_float(p.y);
        acc.x = fmaf(v.x, nm, acc.x); acc.y = fmaf(v.y, nm, acc.y);
        acc.z = fmaf(v.z, nm, acc.z); acc.w = fmaf(v.w, nm, acc.w);
    }
    reinterpret_cast<float4*>(A)[(size_t)node * GRP + lane] = acc;
}

// ---------------- launch ----------------
extern "C" void kernel_launch(void* const* d_in, const int* in_sizes, int n_in,
                              void* d_out, int out_size) {
    const float* x  = (const float*)d_in[0];
    const void*  ei = d_in[1];
    const float* W1 = (const float*)d_in[2];
    const float* b1 = (const float*)d_in[3];
    const float* W2 = (const float*)d_in[4];
    const float* b2 = (const float*)d_in[5];
    const float* W3 = (const float*)d_in[6];
    const float* b3 = (const float*)d_in[7];
    float* out = (float*)d_out;

    float *dinv, *T, *A;
    int *cnt, *off, *cur, *src, *dst, *bsum;
    int2* csr;
    cudaGetSymbolAddress((void**)&dinv, g_dinv);
    cudaGetSymbolAddress((void**)&cnt, g_cnt);
    cudaGetSymbolAddress((void**)&off, g_off);
    cudaGetSymbolAddress((void**)&cur, g_cur);
    cudaGetSymbolAddress((void**)&csr, g_csr);
    cudaGetSymbolAddress((void**)&T, g_T);
    cudaGetSymbolAddress((void**)&A, g_A);
    cudaGetSymbolAddress((void**)&src, g_src);
    cudaGetSymbolAddress((void**)&dst, g_dst);
    cudaGetSymbolAddress((void**)&bsum, g_bsum);

    const int SMEM128 = (128 * 128 + 64 * 128) * 4;  // 96 KB
    const int SMEM64  = (128 * 64 + 64 * 128) * 4;   // 64 KB
    cudaFuncSetAttribute(gemm_kernel<128, false>,
                         cudaFuncAttributeMaxDynamicSharedMemorySize, SMEM128);
    cudaFuncSetAttribute(gemm_kernel<128, true>,
                         cudaFuncAttributeMaxDynamicSharedMemorySize, SMEM128);
    cudaFuncSetAttribute(gemm_kernel<64, true>,
                         cudaFuncAttributeMaxDynamicSharedMemorySize, SMEM64);

    const int N = N_NODES;
    const int E = N_EDGES;
    const int eb = (E + 255) / 256;
    const int nb = (N + 255) / 256;   // 391 blocks <= 512 (scan2 capacity)
    const int gb = (N + 63) / 64;

    // 1-3: minimal prefix so that launch #4 (the ncu capture slot) is the L1 GEMM
    zero_cnt_kernel<<<nb, 256>>>(cnt, N);
    convert_count_kernel<<<eb, 256>>>(ei, src, dst, cnt, E);
    scan1_dinv_kernel<<<nb, 256>>>(cnt, off, bsum, dinv, N);
    // 4: layer-1 GEMM (no dependencies beyond inputs) — profiled launch
    gemm_kernel<128, false><<<gb, 256, SMEM128>>>(x, W1, T, N);
    // 5-7: finish CSR build
    scan2_kernel<<<1, 512>>>(bsum, nb);
    scan3_kernel<<<nb, 256>>>(off, cur, bsum, N);
    csr_build_kernel<<<eb, 256>>>(src, dst, dinv, cur, csr, E);
    // 8: layer-1 aggregation (self-loop + bias fused here)
    agg_kernel<128><<<(N + 7) / 8, 256>>>(off, cnt, csr, T, b1, dinv, A, N);
    // 9-10: layer 2
    gemm_kernel<128, true><<<gb, 256, SMEM128>>>(A, W2, T, N);
    agg_kernel<128><<<(N + 7) / 8, 256>>>(off, cnt, csr, T, b2, dinv, A, N);
    // 11-12: layer 3 -> d_out (agg writes every element of out)
    gemm_kernel<64, true><<<gb, 256, SMEM64>>>(A, W3, T, N);
    agg_kernel<64><<<(N + 15) / 16, 256>>>(off, cnt, csr, T, b3, dinv, out, N);
}